// round 11
// baseline (speedup 1.0000x reference)
#include <cuda_runtime.h>
#include <cuda_fp16.h>
#include <cstdint>

// ============================================================================
// LinearWithLoRA on GB300 (PTX target sm_103 baseline: NO tcgen05/TMEM).
// Fold LoRA into W (rank-16), then one fp16 mma.sync GEMM, fp32 accumulate:
//   out[8192,2048] = x[8192,2048] @ W_eff[2048,2048]^T + b
// R8 ncu: tensor=70.3%, smem port ~100% (LDSM redundancy) co-binding.
// This round: warp tile 64x32 -> 64x64 (4 warps / 128 threads per CTA),
// halves A-fragment redundancy -> smem port ~75%, tensor headroom to ~90%.
// ============================================================================

#define M_TOTAL 8192
#define N_TOTAL 2048
#define K_TOTAL 2048
#define BM 128
#define BN 128
#define BK 64                       // fp16 per K-chunk (128 B/row, swizzled)
#define NCHUNK (K_TOTAL / BK)       // 32
#define NSTAGE 3
#define NTHREADS 128                // 4 warps: 2(M) x 2(N), warp tile 64x64

#define STAGE_BYTES 32768           // A 16K + B 16K
#define OFF_A 0
#define OFF_B 16384
#define SMEM_TOTAL (NSTAGE * STAGE_BYTES)   // 96KB -> 2 CTAs/SM (192KB)

// ---- scratch (static device globals; allocation is forbidden) ----
__device__ __align__(16) __half g_xh[(size_t)M_TOTAL * K_TOTAL];
__device__ __align__(16) __half g_wh[(size_t)N_TOTAL * K_TOTAL];

// ---- helpers ----
__device__ __forceinline__ uint32_t smem_u32(const void* p) {
    uint32_t a;
    asm("{ .reg .u64 t; cvta.to.shared.u64 t, %1; cvt.u32.u64 %0, t; }"
        : "=r"(a) : "l"(p));
    return a;
}

__device__ __forceinline__ void cp16(uint32_t dst, const void* src) {
    asm volatile("cp.async.cg.shared.global [%0], [%1], 16;" :: "r"(dst), "l"(src));
}

// ldmatrix x4: 4 8x8 b16 matrices, one 16B-row address per lane
__device__ __forceinline__ void ldsm4(uint32_t& r0, uint32_t& r1,
                                      uint32_t& r2, uint32_t& r3, uint32_t addr) {
    asm volatile("ldmatrix.sync.aligned.m8n8.x4.shared.b16 {%0,%1,%2,%3}, [%4];"
                 : "=r"(r0), "=r"(r1), "=r"(r2), "=r"(r3) : "r"(addr));
}

// D += A*B, m16n8k16 fp16 inputs fp32 accum
__device__ __forceinline__ void mma16816(float* d, const uint32_t* a, const uint32_t* b) {
    asm volatile(
        "mma.sync.aligned.m16n8k16.row.col.f32.f16.f16.f32 "
        "{%0,%1,%2,%3}, {%4,%5,%6,%7}, {%8,%9}, {%0,%1,%2,%3};"
        : "+f"(d[0]), "+f"(d[1]), "+f"(d[2]), "+f"(d[3])
        : "r"(a[0]), "r"(a[1]), "r"(a[2]), "r"(a[3]), "r"(b[0]), "r"(b[1]));
}

// ============================================================================
// Fused prep: one kernel, branch on blockIdx. x-blocks then W-blocks.
// (2 launches/call => ncu -s 5 -c 1 keeps sampling call 3's gemm_kernel)
// ============================================================================
struct H4 { __half2 a, b; };   // 8 bytes

__device__ __forceinline__ H4 to_h4(float4 v) {
    H4 h;
    h.a = __floats2half2_rn(v.x, v.y);
    h.b = __floats2half2_rn(v.z, v.w);
    return h;
}

#define XBLKS ((M_TOTAL * K_TOTAL / 4) / 256)   // 16384
#define WBLKS ((N_TOTAL * K_TOTAL / 4) / 256)   // 4096

__global__ void prep_kernel(const float4* __restrict__ x,
                            const float4* __restrict__ W,
                            const float* __restrict__ lA,
                            const float* __restrict__ lB) {
    const int bid = blockIdx.x;
    if (bid < XBLKS) {
        int idx = bid * 256 + threadIdx.x;            // over 8192*2048/4
        ((H4*)g_xh)[idx] = to_h4(x[idx]);
    } else {
        int idx = (bid - XBLKS) * 256 + threadIdx.x;  // over 2048*2048/4
        int o = idx >> 9;                             // 512 float4 per row
        int d = (idx & 511) * 4;
        float4 w = W[idx];
        float a0 = 0.f, a1 = 0.f, a2 = 0.f, a3 = 0.f;
#pragma unroll
        for (int r = 0; r < 16; r++) {
            float bb = lB[o * 16 + r];
            const float4 av = *(const float4*)(lA + r * 2048 + d);
            a0 += bb * av.x; a1 += bb * av.y; a2 += bb * av.z; a3 += bb * av.w;
        }
        w.x += 2.0f * a0; w.y += 2.0f * a1;           // SCALING = 32/16
        w.z += 2.0f * a2; w.w += 2.0f * a3;
        ((H4*)g_wh)[idx] = to_h4(w);
    }
}

// ============================================================================
// GEMM: CTA 128x128, 4 warps as 2(M) x 2(N), warp tile 64x64.
// SMEM: row = 128 B (64 fp16), chunk-XOR swizzle:
//   byte(row, chunk16) = row*128 + (chunk ^ (row&7))*16   -> LDSM conflict-free
// 3-stage cp.async ring; 2 CTAs/SM decouple per-chunk barriers.
// ============================================================================
__device__ __forceinline__ void load_stage(uint32_t sbase, int kc,
                                           int mBase, int nBase, int tid) {
    const int kcol = kc * BK;
#pragma unroll
    for (int i = 0; i < 8; i++) {                 // A: 128 rows x 8 x 16B
        int idx = tid + i * NTHREADS;
        int row = idx >> 3;
        int c = idx & 7;
        uint32_t sw = (uint32_t)(c ^ (row & 7)) * 16u + (uint32_t)row * 128u;
        cp16(sbase + OFF_A + sw, g_xh + (size_t)(mBase + row) * K_TOTAL + kcol + c * 8);
    }
#pragma unroll
    for (int i = 0; i < 8; i++) {                 // B: 128 rows x 8 x 16B
        int idx = tid + i * NTHREADS;
        int row = idx >> 3;
        int c = idx & 7;
        uint32_t sw = (uint32_t)(c ^ (row & 7)) * 16u + (uint32_t)row * 128u;
        cp16(sbase + OFF_B + sw, g_wh + (size_t)(nBase + row) * K_TOTAL + kcol + c * 8);
    }
    asm volatile("cp.async.commit_group;" ::: "memory");
}

__global__ void __launch_bounds__(NTHREADS, 2)
gemm_kernel(const float* __restrict__ bias, float* __restrict__ out) {
    extern __shared__ char smem[];
    const uint32_t sbase = smem_u32(smem);
    const int tid = threadIdx.x;
    const int lane = tid & 31;
    const int wid = tid >> 5;
    const int warpM = wid >> 1;                  // 0..1  -> 64-row slice
    const int warpN = wid & 1;                   // 0..1  -> 64-col slice
    const int mBase = blockIdx.y * BM;
    const int nBase = blockIdx.x * BN;

    float acc[4][8][4];                          // [mt][nt][frag]
#pragma unroll
    for (int i = 0; i < 4; i++)
#pragma unroll
        for (int j = 0; j < 8; j++)
#pragma unroll
            for (int k = 0; k < 4; k++) acc[i][j][k] = 0.f;

    // per-lane ldmatrix address components (hoisted)
    // A: row = warpM*64 + mt*16 + (lane & 15); chunk = 2*ks + (lane >> 4)
    //    -> matrices {r0-7/klo, r8-15/klo, r0-7/khi, r8-15/khi} = a0..a3
    const int aRow = warpM * 64 + (lane & 15);
    const int aChunkOff = lane >> 4;
    // B: row = warpN*64 + ntp*16 + ((lane>>4)<<3) + (lane & 7)
    //    chunk = 2*ks + ((lane>>3)&1)  -> per n8-tile {klo, khi}
    const int bRow = warpN * 64 + ((lane >> 4) << 3) + (lane & 7);
    const int bChunkOff = (lane >> 3) & 1;

    // prologue: stages 0,1 in flight
    load_stage(sbase + 0 * STAGE_BYTES, 0, mBase, nBase, tid);
    load_stage(sbase + 1 * STAGE_BYTES, 1, mBase, nBase, tid);

    int s = 0;
    for (int c = 0; c < NCHUNK; c++) {
        // arrival guarantee for chunk c (tail: only group c is in flight)
        if (c == NCHUNK - 1) {
            asm volatile("cp.async.wait_group 0;" ::: "memory");
        } else {
            asm volatile("cp.async.wait_group 1;" ::: "memory");
        }
        __syncthreads();   // all warps done reading the buffer we refill below

        if (c + 2 < NCHUNK) {
            int s2 = s + 2; if (s2 >= NSTAGE) s2 -= NSTAGE;
            load_stage(sbase + s2 * STAGE_BYTES, c + 2, mBase, nBase, tid);
        }

        const uint32_t stA = sbase + s * STAGE_BYTES + OFF_A;
        const uint32_t stB = sbase + s * STAGE_BYTES + OFF_B;

#pragma unroll
        for (int ks = 0; ks < 4; ks++) {
            uint32_t a[4][4];
            uint32_t b[8][2];
#pragma unroll
            for (int mt = 0; mt < 4; mt++) {
                int row = aRow + mt * 16;
                int ch = 2 * ks + aChunkOff;
                uint32_t addr = stA + (uint32_t)row * 128u
                              + (uint32_t)((ch ^ (row & 7)) << 4);
                ldsm4(a[mt][0], a[mt][1], a[mt][2], a[mt][3], addr);
            }
#pragma unroll
            for (int ntp = 0; ntp < 4; ntp++) {
                int row = bRow + ntp * 16;
                int ch = 2 * ks + bChunkOff;
                uint32_t addr = stB + (uint32_t)row * 128u
                              + (uint32_t)((ch ^ (row & 7)) << 4);
                ldsm4(b[2 * ntp][0], b[2 * ntp][1], b[2 * ntp + 1][0], b[2 * ntp + 1][1], addr);
            }
#pragma unroll
            for (int mt = 0; mt < 4; mt++)
#pragma unroll
                for (int nt = 0; nt < 8; nt++)
                    mma16816(acc[mt][nt], a[mt], b[nt]);
        }

        if (++s >= NSTAGE) s = 0;
    }

    // ---- epilogue: registers -> out (+bias), float2 per frag-pair ----
    // frag: d0,d1 = (row = lane/4,     col = 2*(lane%4)+{0,1})
    //       d2,d3 = (row = lane/4 + 8, col same)
    {
        const int rBase = mBase + warpM * 64 + (lane >> 2);
        const int cBase = nBase + warpN * 64 + 2 * (lane & 3);
        float2 bv[8];
#pragma unroll
        for (int nt = 0; nt < 8; nt++) {
            bv[nt].x = __ldg(bias + cBase + nt * 8);
            bv[nt].y = __ldg(bias + cBase + nt * 8 + 1);
        }
#pragma unroll
        for (int mt = 0; mt < 4; mt++) {
            const size_t r0 = (size_t)(rBase + mt * 16) * N_TOTAL;
            const size_t r1 = r0 + 8 * N_TOTAL;
#pragma unroll
            for (int nt = 0; nt < 8; nt++) {
                const int col = cBase + nt * 8;
                float2 v0 = { acc[mt][nt][0] + bv[nt].x, acc[mt][nt][1] + bv[nt].y };
                float2 v1 = { acc[mt][nt][2] + bv[nt].x, acc[mt][nt][3] + bv[nt].y };
                *(float2*)(out + r0 + col) = v0;
                *(float2*)(out + r1 + col) = v1;
            }
        }
    }
}

// ============================================================================
// kernel_launch
// ============================================================================
extern "C" void kernel_launch(void* const* d_in, const int* in_sizes, int n_in,
                              void* d_out, int out_size) {
    const float* x  = (const float*)d_in[0];   // [4,2048,2048] -> [8192,2048]
    const float* W  = (const float*)d_in[1];   // [2048,2048]
    const float* b  = (const float*)d_in[2];   // [2048]
    const float* lA = (const float*)d_in[3];   // [16,2048]
    const float* lB = (const float*)d_in[4];   // [2048,16]
    float* out = (float*)d_out;

    prep_kernel<<<XBLKS + WBLKS, 256>>>((const float4*)x, (const float4*)W, lA, lB);

    cudaFuncSetAttribute(gemm_kernel,
                         cudaFuncAttributeMaxDynamicSharedMemorySize, SMEM_TOTAL);
    // x-fastest: 16 n-blocks sweep per m-row; W (8MB fp16) stays L2-resident
    dim3 grid(N_TOTAL / BN, M_TOTAL / BM);     // (16, 64)
    gemm_kernel<<<grid, NTHREADS, SMEM_TOTAL>>>(b, out);
}

// round 12
// speedup vs baseline: 1.0430x; 1.0430x over previous
#include <cuda_runtime.h>
#include <cuda_fp16.h>
#include <cstdint>

// ============================================================================
// LinearWithLoRA on GB300 (PTX target sm_103 baseline: NO tcgen05/TMEM).
// Fold LoRA into W (rank-16), then one fp16 mma.sync GEMM, fp32 accumulate:
//   out[8192,2048] = x[8192,2048] @ W_eff[2048,2048]^T + b
// R8/R11: tensor pinned at 70% across 2 very different tiles -> bottleneck is
// the per-chunk barrier bubble (LDSM after sync, pipe drained), NOT smem port.
// This round: CUTLASS-sm80-style pipelined mainloop — fragment double buffer,
// barrier at ks3 placed BEFORE next-chunk ks0 prefetch, mma resumes instantly.
// ============================================================================

#define M_TOTAL 8192
#define N_TOTAL 2048
#define K_TOTAL 2048
#define BM 128
#define BN 128
#define BK 64                       // fp16 per K-chunk (128 B/row, swizzled)
#define NCHUNK (K_TOTAL / BK)       // 32
#define NSTAGE 3
#define NTHREADS 128                // 4 warps: 2(M) x 2(N), warp tile 64x64

#define STAGE_BYTES 32768           // A 16K + B 16K
#define OFF_A 0
#define OFF_B 16384
#define SMEM_TOTAL (NSTAGE * STAGE_BYTES)   // 96KB -> 2 CTAs/SM (192KB)

// ---- scratch (static device globals; allocation is forbidden) ----
__device__ __align__(16) __half g_xh[(size_t)M_TOTAL * K_TOTAL];
__device__ __align__(16) __half g_wh[(size_t)N_TOTAL * K_TOTAL];

// ---- helpers ----
__device__ __forceinline__ uint32_t smem_u32(const void* p) {
    uint32_t a;
    asm("{ .reg .u64 t; cvta.to.shared.u64 t, %1; cvt.u32.u64 %0, t; }"
        : "=r"(a) : "l"(p));
    return a;
}

__device__ __forceinline__ void cp16(uint32_t dst, const void* src) {
    asm volatile("cp.async.cg.shared.global [%0], [%1], 16;" :: "r"(dst), "l"(src));
}

// ldmatrix x4: 4 8x8 b16 matrices, one 16B-row address per lane
__device__ __forceinline__ void ldsm4(uint32_t& r0, uint32_t& r1,
                                      uint32_t& r2, uint32_t& r3, uint32_t addr) {
    asm volatile("ldmatrix.sync.aligned.m8n8.x4.shared.b16 {%0,%1,%2,%3}, [%4];"
                 : "=r"(r0), "=r"(r1), "=r"(r2), "=r"(r3) : "r"(addr));
}

// D += A*B, m16n8k16 fp16 inputs fp32 accum
__device__ __forceinline__ void mma16816(float* d, const uint32_t* a, const uint32_t* b) {
    asm volatile(
        "mma.sync.aligned.m16n8k16.row.col.f32.f16.f16.f32 "
        "{%0,%1,%2,%3}, {%4,%5,%6,%7}, {%8,%9}, {%0,%1,%2,%3};"
        : "+f"(d[0]), "+f"(d[1]), "+f"(d[2]), "+f"(d[3])
        : "r"(a[0]), "r"(a[1]), "r"(a[2]), "r"(a[3]), "r"(b[0]), "r"(b[1]));
}

// ============================================================================
// Fused prep: one kernel, branch on blockIdx. x-blocks then W-blocks.
// ============================================================================
struct H4 { __half2 a, b; };   // 8 bytes

__device__ __forceinline__ H4 to_h4(float4 v) {
    H4 h;
    h.a = __floats2half2_rn(v.x, v.y);
    h.b = __floats2half2_rn(v.z, v.w);
    return h;
}

#define XBLKS ((M_TOTAL * K_TOTAL / 4) / 256)   // 16384
#define WBLKS ((N_TOTAL * K_TOTAL / 4) / 256)   // 4096

__global__ void prep_kernel(const float4* __restrict__ x,
                            const float4* __restrict__ W,
                            const float* __restrict__ lA,
                            const float* __restrict__ lB) {
    const int bid = blockIdx.x;
    if (bid < XBLKS) {
        int idx = bid * 256 + threadIdx.x;            // over 8192*2048/4
        ((H4*)g_xh)[idx] = to_h4(x[idx]);
    } else {
        int idx = (bid - XBLKS) * 256 + threadIdx.x;  // over 2048*2048/4
        int o = idx >> 9;                             // 512 float4 per row
        int d = (idx & 511) * 4;
        float4 w = W[idx];
        float a0 = 0.f, a1 = 0.f, a2 = 0.f, a3 = 0.f;
#pragma unroll
        for (int r = 0; r < 16; r++) {
            float bb = lB[o * 16 + r];
            const float4 av = *(const float4*)(lA + r * 2048 + d);
            a0 += bb * av.x; a1 += bb * av.y; a2 += bb * av.z; a3 += bb * av.w;
        }
        w.x += 2.0f * a0; w.y += 2.0f * a1;           // SCALING = 32/16
        w.z += 2.0f * a2; w.w += 2.0f * a3;
        ((H4*)g_wh)[idx] = to_h4(w);
    }
}

// ============================================================================
// GEMM: CTA 128x128, 4 warps as 2(M) x 2(N), warp tile 64x64.
// SMEM: row = 128 B (64 fp16), chunk-XOR swizzle:
//   byte(row, chunk16) = row*128 + (chunk ^ (row&7))*16   -> LDSM conflict-free
// Pipelined mainloop: fragment double buffer; per-chunk barrier at ks3,
// BEFORE the next-chunk ks0 prefetch, so the tensor pipe never waits on LDSM.
// ============================================================================
__device__ __forceinline__ void load_stage(uint32_t sbase, int kc,
                                           int mBase, int nBase, int tid) {
    const int kcol = kc * BK;
#pragma unroll
    for (int i = 0; i < 8; i++) {                 // A: 128 rows x 8 x 16B
        int idx = tid + i * NTHREADS;
        int row = idx >> 3;
        int c = idx & 7;
        uint32_t sw = (uint32_t)(c ^ (row & 7)) * 16u + (uint32_t)row * 128u;
        cp16(sbase + OFF_A + sw, g_xh + (size_t)(mBase + row) * K_TOTAL + kcol + c * 8);
    }
#pragma unroll
    for (int i = 0; i < 8; i++) {                 // B: 128 rows x 8 x 16B
        int idx = tid + i * NTHREADS;
        int row = idx >> 3;
        int c = idx & 7;
        uint32_t sw = (uint32_t)(c ^ (row & 7)) * 16u + (uint32_t)row * 128u;
        cp16(sbase + OFF_B + sw, g_wh + (size_t)(nBase + row) * K_TOTAL + kcol + c * 8);
    }
    asm volatile("cp.async.commit_group;" ::: "memory");
}

__global__ void __launch_bounds__(NTHREADS, 2)
gemm_kernel(const float* __restrict__ bias, float* __restrict__ out) {
    extern __shared__ char smem[];
    const uint32_t sbase = smem_u32(smem);
    const int tid = threadIdx.x;
    const int lane = tid & 31;
    const int wid = tid >> 5;
    const int warpM = wid >> 1;                  // 0..1  -> 64-row slice
    const int warpN = wid & 1;                   // 0..1  -> 64-col slice
    const int mBase = blockIdx.y * BM;
    const int nBase = blockIdx.x * BN;

    float acc[4][8][4];                          // [mt][nt][frag]
#pragma unroll
    for (int i = 0; i < 4; i++)
#pragma unroll
        for (int j = 0; j < 8; j++)
#pragma unroll
            for (int k = 0; k < 4; k++) acc[i][j][k] = 0.f;

    // per-lane ldmatrix address components (hoisted)
    // A: row = warpM*64 + mt*16 + (lane & 15); chunk = 2*ks + (lane >> 4)
    const int aRow = warpM * 64 + (lane & 15);
    const int aChunkOff = lane >> 4;
    // B: row = warpN*64 + ntp*16 + ((lane>>4)<<3) + (lane & 7)
    //    chunk = 2*ks + ((lane>>3)&1)
    const int bRow = warpN * 64 + ((lane >> 4) << 3) + (lane & 7);
    const int bChunkOff = (lane >> 3) & 1;

    // double-buffered fragments
    uint32_t a[2][4][4];
    uint32_t b[2][8][2];

    // fragment loader: buf <- (stage base, ks)
#define LDSM_BLOCK(buf, stBase, ksv)                                          \
    do {                                                                      \
        const uint32_t _stA = (stBase) + OFF_A;                               \
        const uint32_t _stB = (stBase) + OFF_B;                               \
        _Pragma("unroll")                                                     \
        for (int mt = 0; mt < 4; mt++) {                                      \
            int row = aRow + mt * 16;                                         \
            int ch = 2 * (ksv) + aChunkOff;                                   \
            uint32_t addr = _stA + (uint32_t)row * 128u                       \
                          + (uint32_t)((ch ^ (row & 7)) << 4);                \
            ldsm4(a[buf][mt][0], a[buf][mt][1], a[buf][mt][2], a[buf][mt][3], \
                  addr);                                                      \
        }                                                                     \
        _Pragma("unroll")                                                     \
        for (int ntp = 0; ntp < 4; ntp++) {                                   \
            int row = bRow + ntp * 16;                                        \
            int ch = 2 * (ksv) + bChunkOff;                                   \
            uint32_t addr = _stB + (uint32_t)row * 128u                       \
                          + (uint32_t)((ch ^ (row & 7)) << 4);                \
            ldsm4(b[buf][2 * ntp][0], b[buf][2 * ntp][1],                     \
                  b[buf][2 * ntp + 1][0], b[buf][2 * ntp + 1][1], addr);      \
        }                                                                     \
    } while (0)

#define MMA_BLOCK(buf)                                                        \
    do {                                                                      \
        _Pragma("unroll")                                                     \
        for (int mt = 0; mt < 4; mt++)                                        \
            _Pragma("unroll")                                                 \
            for (int nt = 0; nt < 8; nt++)                                    \
                mma16816(acc[mt][nt], a[buf][mt], b[buf][nt]);                \
    } while (0)

    // prologue: chunks 0,1 in flight (G0, G1)
    load_stage(sbase + 0 * STAGE_BYTES, 0, mBase, nBase, tid);
    load_stage(sbase + 1 * STAGE_BYTES, 1, mBase, nBase, tid);
    asm volatile("cp.async.wait_group 1;" ::: "memory");   // G0 done
    __syncthreads();                                       // chunk 0 visible
    LDSM_BLOCK(0, sbase + 0 * STAGE_BYTES, 0);             // c0 ks0 -> buf0

    int s = 0;                                             // stage of chunk c
    for (int c = 0; c < NCHUNK; c++) {
        const uint32_t stC = sbase + (uint32_t)s * STAGE_BYTES;
        int s1 = s + 1; if (s1 >= NSTAGE) s1 -= NSTAGE;    // stage of chunk c+1
        int s2 = s + 2; if (s2 >= NSTAGE) s2 -= NSTAGE;    // stage of chunk c+2

        // ks = 0..2: prefetch next ks fragments, then mma current
        LDSM_BLOCK(1, stC, 1);
        MMA_BLOCK(0);
        LDSM_BLOCK(0, stC, 2);
        MMA_BLOCK(1);
        LDSM_BLOCK(1, stC, 3);
        MMA_BLOCK(0);

        // ks = 3: stage transition. Barrier BEFORE next-chunk ks0 prefetch;
        // ks3 fragments (buf1) already in regs -> mma resumes immediately.
        if (c + 1 < NCHUNK) {
            // pending groups here = {G_{c+1}} only (G_{c+2} committed below)
            asm volatile("cp.async.wait_group 0;" ::: "memory");
            __syncthreads();   // chunk c+1 visible to all; stage s2 readers done
            LDSM_BLOCK(0, sbase + (uint32_t)s1 * STAGE_BYTES, 0);
        }
        MMA_BLOCK(1);
        if (c + 2 < NCHUNK)
            load_stage(sbase + (uint32_t)s2 * STAGE_BYTES, c + 2, mBase, nBase, tid);

        s = s1;
    }

    // ---- epilogue: registers -> out (+bias), float2 per frag-pair ----
    {
        const int rBase = mBase + warpM * 64 + (lane >> 2);
        const int cBase = nBase + warpN * 64 + 2 * (lane & 3);
        float2 bv[8];
#pragma unroll
        for (int nt = 0; nt < 8; nt++) {
            bv[nt].x = __ldg(bias + cBase + nt * 8);
            bv[nt].y = __ldg(bias + cBase + nt * 8 + 1);
        }
#pragma unroll
        for (int mt = 0; mt < 4; mt++) {
            const size_t r0 = (size_t)(rBase + mt * 16) * N_TOTAL;
            const size_t r1 = r0 + 8 * N_TOTAL;
#pragma unroll
            for (int nt = 0; nt < 8; nt++) {
                const int col = cBase + nt * 8;
                float2 v0 = { acc[mt][nt][0] + bv[nt].x, acc[mt][nt][1] + bv[nt].y };
                float2 v1 = { acc[mt][nt][2] + bv[nt].x, acc[mt][nt][3] + bv[nt].y };
                *(float2*)(out + r0 + col) = v0;
                *(float2*)(out + r1 + col) = v1;
            }
        }
    }
}

// ============================================================================
// kernel_launch
// ============================================================================
extern "C" void kernel_launch(void* const* d_in, const int* in_sizes, int n_in,
                              void* d_out, int out_size) {
    const float* x  = (const float*)d_in[0];   // [4,2048,2048] -> [8192,2048]
    const float* W  = (const float*)d_in[1];   // [2048,2048]
    const float* b  = (const float*)d_in[2];   // [2048]
    const float* lA = (const float*)d_in[3];   // [16,2048]
    const float* lB = (const float*)d_in[4];   // [2048,16]
    float* out = (float*)d_out;

    prep_kernel<<<XBLKS + WBLKS, 256>>>((const float4*)x, (const float4*)W, lA, lB);

    cudaFuncSetAttribute(gemm_kernel,
                         cudaFuncAttributeMaxDynamicSharedMemorySize, SMEM_TOTAL);
    // x-fastest: 16 n-blocks sweep per m-row; W (8MB fp16) stays L2-resident
    dim3 grid(N_TOTAL / BN, M_TOTAL / BM);     // (16, 64)
    gemm_kernel<<<grid, NTHREADS, SMEM_TOTAL>>>(b, out);
}

// round 14
// speedup vs baseline: 1.0626x; 1.0187x over previous
#include <cuda_runtime.h>
#include <cuda_fp16.h>
#include <cstdint>

// ============================================================================
// LinearWithLoRA on GB300 (PTX target sm_103 baseline: NO tcgen05/TMEM).
// Fold LoRA into W (rank-16), then one fp16 mma.sync GEMM, fp32 accumulate:
//   out[8192,2048] = x[8192,2048] @ W_eff[2048,2048]^T + b
// R12: pipelined mainloop WIN (184.4us, gemm 151.7, tensor 73.9%) but regs=254
// pinned at cap -> scheduler strangled. This round: incremental addressing
// (2 base ptrs + const offsets replace 16 live 64-bit addrs) to free ~30 regs;
// prep widened to 8 floats/thread (2x MLP) to close the 33us non-gemm gap.
// ============================================================================

#define M_TOTAL 8192
#define N_TOTAL 2048
#define K_TOTAL 2048
#define BM 128
#define BN 128
#define BK 64                       // fp16 per K-chunk (128 B/row, swizzled)
#define NCHUNK (K_TOTAL / BK)       // 32
#define NSTAGE 3
#define NTHREADS 128                // 4 warps: 2(M) x 2(N), warp tile 64x64

#define STAGE_BYTES 32768           // A 16K + B 16K
#define OFF_A 0
#define OFF_B 16384
#define SMEM_TOTAL (NSTAGE * STAGE_BYTES)   // 96KB -> 2 CTAs/SM (192KB)

// ---- scratch (static device globals; allocation is forbidden) ----
__device__ __align__(16) __half g_xh[(size_t)M_TOTAL * K_TOTAL];
__device__ __align__(16) __half g_wh[(size_t)N_TOTAL * K_TOTAL];

// ---- helpers ----
__device__ __forceinline__ uint32_t smem_u32(const void* p) {
    uint32_t a;
    asm("{ .reg .u64 t; cvta.to.shared.u64 t, %1; cvt.u32.u64 %0, t; }"
        : "=r"(a) : "l"(p));
    return a;
}

__device__ __forceinline__ void cp16(uint32_t dst, const void* src) {
    asm volatile("cp.async.cg.shared.global [%0], [%1], 16;" :: "r"(dst), "l"(src));
}

// ldmatrix x4: 4 8x8 b16 matrices, one 16B-row address per lane
__device__ __forceinline__ void ldsm4(uint32_t& r0, uint32_t& r1,
                                      uint32_t& r2, uint32_t& r3, uint32_t addr) {
    asm volatile("ldmatrix.sync.aligned.m8n8.x4.shared.b16 {%0,%1,%2,%3}, [%4];"
                 : "=r"(r0), "=r"(r1), "=r"(r2), "=r"(r3) : "r"(addr));
}

// D += A*B, m16n8k16 fp16 inputs fp32 accum
__device__ __forceinline__ void mma16816(float* d, const uint32_t* a, const uint32_t* b) {
    asm volatile(
        "mma.sync.aligned.m16n8k16.row.col.f32.f16.f16.f32 "
        "{%0,%1,%2,%3}, {%4,%5,%6,%7}, {%8,%9}, {%0,%1,%2,%3};"
        : "+f"(d[0]), "+f"(d[1]), "+f"(d[2]), "+f"(d[3])
        : "r"(a[0]), "r"(a[1]), "r"(a[2]), "r"(a[3]), "r"(b[0]), "r"(b[1]));
}

// ============================================================================
// Fused prep, 8 floats/thread: 2x float4 loads, one 16B store per array.
// Same per-element arithmetic/rounding as before -> bit-identical outputs.
// ============================================================================
struct H4 { __half2 a, b; };   // 8 bytes
struct __align__(16) H8 { H4 lo, hi; };   // 16 bytes

__device__ __forceinline__ H4 to_h4(float4 v) {
    H4 h;
    h.a = __floats2half2_rn(v.x, v.y);
    h.b = __floats2half2_rn(v.z, v.w);
    return h;
}

#define XBLKS ((M_TOTAL * K_TOTAL / 8) / 256)   // 8192
#define WBLKS ((N_TOTAL * K_TOTAL / 8) / 256)   // 2048

__global__ void prep_kernel(const float4* __restrict__ x,
                            const float4* __restrict__ W,
                            const float* __restrict__ lA,
                            const float* __restrict__ lB) {
    const int bid = blockIdx.x;
    if (bid < XBLKS) {
        int idx = bid * 256 + threadIdx.x;            // over 8192*2048/8
        float4 v0 = x[2 * idx], v1 = x[2 * idx + 1];
        H8 h = { to_h4(v0), to_h4(v1) };
        ((H8*)g_xh)[idx] = h;
    } else {
        int idx = (bid - XBLKS) * 256 + threadIdx.x;  // over 2048*2048/8
        int o = idx >> 8;                             // 256 groups of 8 per row
        int d = (idx & 255) * 8;
        float4 w0 = W[2 * idx], w1 = W[2 * idx + 1];
        float a0 = 0.f, a1 = 0.f, a2 = 0.f, a3 = 0.f;
        float a4 = 0.f, a5 = 0.f, a6 = 0.f, a7 = 0.f;
#pragma unroll
        for (int r = 0; r < 16; r++) {
            float bb = lB[o * 16 + r];
            const float4 av0 = *(const float4*)(lA + r * 2048 + d);
            const float4 av1 = *(const float4*)(lA + r * 2048 + d + 4);
            a0 += bb * av0.x; a1 += bb * av0.y; a2 += bb * av0.z; a3 += bb * av0.w;
            a4 += bb * av1.x; a5 += bb * av1.y; a6 += bb * av1.z; a7 += bb * av1.w;
        }
        w0.x += 2.0f * a0; w0.y += 2.0f * a1;         // SCALING = 32/16
        w0.z += 2.0f * a2; w0.w += 2.0f * a3;
        w1.x += 2.0f * a4; w1.y += 2.0f * a5;
        w1.z += 2.0f * a6; w1.w += 2.0f * a7;
        H8 h = { to_h4(w0), to_h4(w1) };
        ((H8*)g_wh)[idx] = h;
    }
}

// ============================================================================
// GEMM: CTA 128x128, 4 warps as 2(M) x 2(N), warp tile 64x64.
// SMEM: row = 128 B (64 fp16), chunk-XOR swizzle (conflict-free LDSM).
// Pipelined mainloop (fragment double buffer, barrier before ks0-prefetch).
// Incremental cp.async addressing: per-thread row8 = tid>>3 is invariant;
// the 8 loads step by 65536 B in gmem / 2048 B in smem; chunks step 128 B.
// ============================================================================
__global__ void __launch_bounds__(NTHREADS, 2)
gemm_kernel(const float* __restrict__ bias, float* __restrict__ out) {
    extern __shared__ char smem[];
    const uint32_t sbase = smem_u32(smem);
    const int tid = threadIdx.x;
    const int lane = tid & 31;
    const int wid = tid >> 5;
    const int warpM = wid >> 1;                  // 0..1  -> 64-row slice
    const int warpN = wid & 1;                   // 0..1  -> 64-col slice
    const int mBase = blockIdx.y * BM;
    const int nBase = blockIdx.x * BN;

    // ---- incremental cp.async bases (replaces 16 live 64-bit addresses) ----
    const int row8 = tid >> 3;                   // 0..15; +16 per i
    const int c8 = tid & 7;
    const uint32_t dOff = (uint32_t)((c8 ^ (row8 & 7)) << 4) + (uint32_t)row8 * 128u;
    const char* aSrc0 = (const char*)g_xh
        + ((size_t)(mBase + row8) * K_TOTAL + c8 * 8) * 2;
    const char* bSrc0 = (const char*)g_wh
        + ((size_t)(nBase + row8) * K_TOTAL + c8 * 8) * 2;

#define LOAD_STAGE(stBase, kc)                                                \
    do {                                                                      \
        const char* _as = aSrc0 + (kc) * 128;                                 \
        const char* _bs = bSrc0 + (kc) * 128;                                 \
        const uint32_t _ad = (stBase) + OFF_A + dOff;                         \
        const uint32_t _bd = (stBase) + OFF_B + dOff;                         \
        _Pragma("unroll")                                                     \
        for (int i = 0; i < 8; i++) cp16(_ad + i * 2048, _as + i * 65536);    \
        _Pragma("unroll")                                                     \
        for (int i = 0; i < 8; i++) cp16(_bd + i * 2048, _bs + i * 65536);    \
        asm volatile("cp.async.commit_group;" ::: "memory");                  \
    } while (0)

    float acc[4][8][4];                          // [mt][nt][frag]
#pragma unroll
    for (int i = 0; i < 4; i++)
#pragma unroll
        for (int j = 0; j < 8; j++)
#pragma unroll
            for (int k = 0; k < 4; k++) acc[i][j][k] = 0.f;

    // per-lane ldmatrix address components (hoisted)
    const int aRow = warpM * 64 + (lane & 15);
    const int aChunkOff = lane >> 4;
    const int bRow = warpN * 64 + ((lane >> 4) << 3) + (lane & 7);
    const int bChunkOff = (lane >> 3) & 1;

    // double-buffered fragments
    uint32_t a[2][4][4];
    uint32_t b[2][8][2];

#define LDSM_BLOCK(buf, stBase, ksv)                                          \
    do {                                                                      \
        const uint32_t _stA = (stBase) + OFF_A;                               \
        const uint32_t _stB = (stBase) + OFF_B;                               \
        _Pragma("unroll")                                                     \
        for (int mt = 0; mt < 4; mt++) {                                      \
            int row = aRow + mt * 16;                                         \
            int ch = 2 * (ksv) + aChunkOff;                                   \
            uint32_t addr = _stA + (uint32_t)row * 128u                       \
                          + (uint32_t)((ch ^ (row & 7)) << 4);                \
            ldsm4(a[buf][mt][0], a[buf][mt][1], a[buf][mt][2], a[buf][mt][3], \
                  addr);                                                      \
        }                                                                     \
        _Pragma("unroll")                                                     \
        for (int ntp = 0; ntp < 4; ntp++) {                                   \
            int row = bRow + ntp * 16;                                        \
            int ch = 2 * (ksv) + bChunkOff;                                   \
            uint32_t addr = _stB + (uint32_t)row * 128u                       \
                          + (uint32_t)((ch ^ (row & 7)) << 4);                \
            ldsm4(b[buf][2 * ntp][0], b[buf][2 * ntp][1],                     \
                  b[buf][2 * ntp + 1][0], b[buf][2 * ntp + 1][1], addr);      \
        }                                                                     \
    } while (0)

#define MMA_BLOCK(buf)                                                        \
    do {                                                                      \
        _Pragma("unroll")                                                     \
        for (int mt = 0; mt < 4; mt++)                                        \
            _Pragma("unroll")                                                 \
            for (int nt = 0; nt < 8; nt++)                                    \
                mma16816(acc[mt][nt], a[buf][mt], b[buf][nt]);                \
    } while (0)

    // prologue: chunks 0,1 in flight (G0, G1)
    LOAD_STAGE(sbase + 0 * STAGE_BYTES, 0);
    LOAD_STAGE(sbase + 1 * STAGE_BYTES, 1);
    asm volatile("cp.async.wait_group 1;" ::: "memory");   // G0 done
    __syncthreads();                                       // chunk 0 visible
    LDSM_BLOCK(0, sbase + 0 * STAGE_BYTES, 0);             // c0 ks0 -> buf0

    int s = 0;                                             // stage of chunk c
    for (int c = 0; c < NCHUNK; c++) {
        const uint32_t stC = sbase + (uint32_t)s * STAGE_BYTES;
        int s1 = s + 1; if (s1 >= NSTAGE) s1 -= NSTAGE;    // stage of chunk c+1
        int s2 = s + 2; if (s2 >= NSTAGE) s2 -= NSTAGE;    // stage of chunk c+2

        // ks = 0..2: prefetch next ks fragments, then mma current
        LDSM_BLOCK(1, stC, 1);
        MMA_BLOCK(0);
        LDSM_BLOCK(0, stC, 2);
        MMA_BLOCK(1);
        LDSM_BLOCK(1, stC, 3);
        MMA_BLOCK(0);

        // ks = 3: stage transition. Barrier BEFORE next-chunk ks0 prefetch;
        // ks3 fragments (buf1) already in regs -> mma resumes immediately.
        if (c + 1 < NCHUNK) {
            // pending groups here = {G_{c+1}} only (G_{c+2} committed below)
            asm volatile("cp.async.wait_group 0;" ::: "memory");
            __syncthreads();   // chunk c+1 visible; stage s2 readers done
            LDSM_BLOCK(0, sbase + (uint32_t)s1 * STAGE_BYTES, 0);
        }
        MMA_BLOCK(1);
        if (c + 2 < NCHUNK)
            LOAD_STAGE(sbase + (uint32_t)s2 * STAGE_BYTES, c + 2);

        s = s1;
    }

    // ---- epilogue: registers -> out (+bias), float2 per frag-pair ----
    {
        const int rBase = mBase + warpM * 64 + (lane >> 2);
        const int cBase = nBase + warpN * 64 + 2 * (lane & 3);
        float2 bv[8];
#pragma unroll
        for (int nt = 0; nt < 8; nt++) {
            bv[nt].x = __ldg(bias + cBase + nt * 8);
            bv[nt].y = __ldg(bias + cBase + nt * 8 + 1);
        }
#pragma unroll
        for (int mt = 0; mt < 4; mt++) {
            const size_t r0 = (size_t)(rBase + mt * 16) * N_TOTAL;
            const size_t r1 = r0 + 8 * N_TOTAL;
#pragma unroll
            for (int nt = 0; nt < 8; nt++) {
                const int col = cBase + nt * 8;
                float2 v0 = { acc[mt][nt][0] + bv[nt].x, acc[mt][nt][1] + bv[nt].y };
                float2 v1 = { acc[mt][nt][2] + bv[nt].x, acc[mt][nt][3] + bv[nt].y };
                *(float2*)(out + r0 + col) = v0;
                *(float2*)(out + r1 + col) = v1;
            }
        }
    }
}

// ============================================================================
// kernel_launch
// ============================================================================
extern "C" void kernel_launch(void* const* d_in, const int* in_sizes, int n_in,
                              void* d_out, int out_size) {
    const float* x  = (const float*)d_in[0];   // [4,2048,2048] -> [8192,2048]
    const float* W  = (const float*)d_in[1];   // [2048,2048]
    const float* b  = (const float*)d_in[2];   // [2048]
    const float* lA = (const float*)d_in[3];   // [16,2048]
    const float* lB = (const float*)d_in[4];   // [2048,16]
    float* out = (float*)d_out;

    prep_kernel<<<XBLKS + WBLKS, 256>>>((const float4*)x, (const float4*)W, lA, lB);

    cudaFuncSetAttribute(gemm_kernel,
                         cudaFuncAttributeMaxDynamicSharedMemorySize, SMEM_TOTAL);
    // x-fastest: 16 n-blocks sweep per m-row; W (8MB fp16) stays L2-resident
    dim3 grid(N_TOTAL / BN, M_TOTAL / BM);     // (16, 64)
    gemm_kernel<<<grid, NTHREADS, SMEM_TOTAL>>>(b, out);
}